// round 8
// baseline (speedup 1.0000x reference)
#include <cuda_runtime.h>
#include <cstdint>
#include <math.h>

#define L 256
#define D 128
#define H 4
#define DH 32
#define NROW (L * L)
#define LOG2E 1.4426950408889634f

// ---------------- scratch (device globals; no allocations allowed) ----------
__device__ float g_x[NROW * D];      // LayerNorm output (fp32, row-major)
__device__ float g_xp[NROW * D];     // x in tf32 mma A-fragment order
__device__ float g_qp[NROW * D];     // per-(i,h) A-frag Q (scaled by DH^-0.5*log2e)
__device__ float g_kp[NROW * D];     // per-(i,h) B-frag K^T
__device__ float g_vp[NROW * D];     // per-(i,h) B-frag V
__device__ float g_gate[NROW * D];   // sigmoid(x Wg + bg), row-major
__device__ float g_bias[H * NROW];   // biasT[h][j*L + k] (pre-multiplied by log2e)
__device__ float g_goutp[NROW * D];  // gate*attn_out in A-fragment order
__device__ float g_wp[5 * 16 * 1024];// 5 weights in B-fragment order (tf32)

__device__ __forceinline__ float to_tf32(float x) {
    unsigned int u;
    asm("cvt.rna.tf32.f32 %0, %1;" : "=r"(u) : "f"(x));
    return __uint_as_float(u);
}
__device__ __forceinline__ float fast_ex2(float x) {
    float y;
    asm("ex2.approx.ftz.f32 %0, %1;" : "=f"(y) : "f"(x));
    return y;
}

// ---------------- LayerNorm -------------------------------------------------
__global__ __launch_bounds__(256) void ln_kernel(const float* __restrict__ pair,
                                                 const float* __restrict__ ln_w,
                                                 const float* __restrict__ ln_b) {
    int t = threadIdx.x;
    int lane = t & 31;
    int warp = t >> 5;
    int n = blockIdx.x * 8 + warp;
    const float4 xv = *(const float4*)&pair[(size_t)n * D + lane * 4];
    float s  = xv.x + xv.y + xv.z + xv.w;
    float s2 = xv.x * xv.x + xv.y * xv.y + xv.z * xv.z + xv.w * xv.w;
#pragma unroll
    for (int off = 16; off > 0; off >>= 1) {
        s  += __shfl_xor_sync(0xffffffffu, s,  off);
        s2 += __shfl_xor_sync(0xffffffffu, s2, off);
    }
    float mean = s * (1.0f / 128.0f);
    float var  = s2 * (1.0f / 128.0f) - mean * mean;
    float rstd = rsqrtf(var + 1e-5f);
    float4 w4 = *(const float4*)&ln_w[lane * 4];
    float4 b4 = *(const float4*)&ln_b[lane * 4];
    float4 o;
    o.x = (xv.x - mean) * rstd * w4.x + b4.x;
    o.y = (xv.y - mean) * rstd * w4.y + b4.y;
    o.z = (xv.z - mean) * rstd * w4.z + b4.z;
    o.w = (xv.w - mean) * rstd * w4.w + b4.w;
    *(float4*)&g_x[(size_t)n * D + lane * 4] = o;
}

// ---------------- A-operand permute (16-row tiles, D=128) -------------------
__global__ __launch_bounds__(256) void permute_a_kernel(const float* __restrict__ src,
                                                        float* __restrict__ dst) {
    __shared__ float s[16][132];
    int t = threadIdx.x;
    size_t base = (size_t)blockIdx.x * (16 * 128);
#pragma unroll
    for (int it = 0; it < 2; it++) {
        int f4 = t + it * 256;
        int row = f4 >> 5;
        int c4 = f4 & 31;
        float4 v = *(const float4*)&src[base + row * 128 + c4 * 4];
        s[row][c4 * 4 + 0] = v.x;
        s[row][c4 * 4 + 1] = v.y;
        s[row][c4 * 4 + 2] = v.z;
        s[row][c4 * 4 + 3] = v.w;
    }
    __syncthreads();
    int lane = t & 31;
    int w = t >> 5;
    int g  = lane >> 2;
    int tt = lane & 3;
#pragma unroll
    for (int q = 0; q < 2; q++) {
        int ks = w * 2 + q;
        float4 o;
        o.x = to_tf32(s[g][ks * 8 + tt]);
        o.y = to_tf32(s[g + 8][ks * 8 + tt]);
        o.z = to_tf32(s[g][ks * 8 + tt + 4]);
        o.w = to_tf32(s[g + 8][ks * 8 + tt + 4]);
        *(float4*)&dst[base + ks * 128 + lane * 4] = o;
    }
}

// ---------------- W permute -------------------------------------------------
__global__ __launch_bounds__(256) void permute_w_kernel(const float* __restrict__ Wq,
                                                        const float* __restrict__ Wk,
                                                        const float* __restrict__ Wv,
                                                        const float* __restrict__ Wg,
                                                        const float* __restrict__ Wo) {
    const float* srcs[5] = {Wq, Wk, Wv, Wg, Wo};
    const float* W = srcs[blockIdx.x];
    float* dst = g_wp + blockIdx.x * 16384;
    for (int i = threadIdx.x; i < 16384; i += 256) {
        int kk = i >> 7;
        int n  = i & 127;
        int ks = kk >> 3;
        int nt = n >> 3;
        int lane = (n & 7) * 4 + (kk & 3);
        int reg  = (kk >> 2) & 1;
        dst[ks * 1024 + nt * 64 + lane * 2 + reg] = to_tf32(W[i]);
    }
}

// ---------------- fused projection: X @ {Wq,Wk,Wv,Wg}, direct frag output ---
// Block = 128 rows; A fragments resident in smem; loops over 4 weights.
// q/k/v written directly in per-(i,h) attention fragment order via smem
// re-staging; gate written row-major with sigmoid.
__global__ __launch_bounds__(256) void proj_fused_kernel(const float* __restrict__ Xp,
                                                         const float* __restrict__ bg) {
    extern __shared__ float sh[];
    float* Afull = sh;            // 16384 floats (8 m-tiles x 16 ks x 128)
    float* Bs    = sh + 16384;    // 4096 floats (k-chunk of W, then staging)

    int t = threadIdx.x;
    int lane = t & 31;
    int warp = t >> 5;
    int warp_m = warp >> 1;
    int warp_n = warp & 1;
    int g   = lane >> 2;
    int tid = lane & 3;
    int iblk = blockIdx.x >> 1;           // i (pair row)
    int half = blockIdx.x & 1;            // which 128-row half of i
    int m0 = blockIdx.x * 128;

    // stage A fragments (contiguous copy)
    const float* asrc = Xp + (size_t)blockIdx.x * 16384;
#pragma unroll
    for (int it = 0; it < 16; it++) {
        int f4 = t + it * 256;
        *(float4*)&Afull[f4 * 4] = *(const float4*)&asrc[f4 * 4];
    }

    const float qscale = 0.17677669529663687f * LOG2E;

    for (int w = 0; w < 4; w++) {
        float acc[2][8][4];
#pragma unroll
        for (int wm = 0; wm < 2; wm++)
#pragma unroll
            for (int nt = 0; nt < 8; nt++)
#pragma unroll
                for (int r = 0; r < 4; r++) acc[wm][nt][r] = 0.0f;

        const float* wp = g_wp + (size_t)w * 16384;
        for (int c = 0; c < 4; c++) {
            __syncthreads();
#pragma unroll
            for (int it = 0; it < 4; it++) {
                int f4 = t + it * 256;
                *(float4*)&Bs[f4 * 4] = *(const float4*)&wp[c * 4096 + f4 * 4];
            }
            __syncthreads();
#pragma unroll
            for (int ksl = 0; ksl < 4; ksl++) {
                int ksg = c * 4 + ksl;
                uint4 afr[2];
                afr[0] = *(const uint4*)&Afull[(warp_m * 2 + 0) * 2048 + ksg * 128 + lane * 4];
                afr[1] = *(const uint4*)&Afull[(warp_m * 2 + 1) * 2048 + ksg * 128 + lane * 4];
                uint2 bfr[8];
#pragma unroll
                for (int nt = 0; nt < 8; nt++)
                    bfr[nt] = *(const uint2*)&Bs[ksl * 1024 + (warp_n * 8 + nt) * 64 + lane * 2];
#pragma unroll
                for (int wm = 0; wm < 2; wm++)
#pragma unroll
                    for (int nt = 0; nt < 8; nt++) {
                        asm volatile(
                            "mma.sync.aligned.m16n8k8.row.col.f32.tf32.tf32.f32 "
                            "{%0,%1,%2,%3}, {%4,%5,%6,%7}, {%8,%9}, {%0,%1,%2,%3};"
                            : "+f"(acc[wm][nt][0]), "+f"(acc[wm][nt][1]),
                              "+f"(acc[wm][nt][2]), "+f"(acc[wm][nt][3])
                            : "r"(afr[wm].x), "r"(afr[wm].y), "r"(afr[wm].z), "r"(afr[wm].w),
                              "r"(bfr[nt].x), "r"(bfr[nt].y));
                    }
            }
        }
        __syncthreads();

        if (w == 3) {
            // gate: sigmoid(acc + bg[col]), row-major
#pragma unroll
            for (int wm = 0; wm < 2; wm++) {
                int row0 = m0 + warp_m * 32 + wm * 16 + g;
#pragma unroll
                for (int nt = 0; nt < 8; nt++) {
                    int col = warp_n * 64 + nt * 8 + tid * 2;
                    float b0 = bg[col], b1 = bg[col + 1];
                    float v0 = 1.0f / (1.0f + __expf(-(acc[wm][nt][0] + b0)));
                    float v1 = 1.0f / (1.0f + __expf(-(acc[wm][nt][1] + b1)));
                    float v2 = 1.0f / (1.0f + __expf(-(acc[wm][nt][2] + b0)));
                    float v3 = 1.0f / (1.0f + __expf(-(acc[wm][nt][3] + b1)));
                    *(float2*)&g_gate[(size_t)row0 * 128 + col]       = make_float2(v0, v1);
                    *(float2*)&g_gate[(size_t)(row0 + 8) * 128 + col] = make_float2(v2, v3);
                }
            }
        } else {
            // q/k/v: scatter into staging (exact inverse of attn_permute maps),
            // then coalesced copy of 4096 floats to the per-(i,h) buffer.
            float* outbuf = (w == 0) ? g_qp : (w == 1) ? g_kp : g_vp;
            for (int h = 0; h < 4; h++) {
                if (warp_n == (h >> 1)) {
                    int ntbase = (h & 1) * 4;
#pragma unroll
                    for (int wm = 0; wm < 2; wm++) {
#pragma unroll
                        for (int ntl = 0; ntl < 4; ntl++) {
                            int nt = ntbase + ntl;
#pragma unroll
                            for (int r = 0; r < 4; r++) {
                                float a = acc[wm][nt][r];
                                int e = (2 * tid + (r & 1)) & 3;
                                int idx;
                                if (w == 0) {
                                    a *= qscale;
                                    idx = (warp_m * 2 + wm) * 512 + ntl * 128
                                        + (g * 4 + e) * 4 + (r >> 1) + 2 * (tid >> 1);
                                } else if (w == 1) {
                                    idx = (warp_m * 4 + wm * 2 + (r >> 1)) * 256 + ntl * 64
                                        + (g * 4 + e) * 2 + (tid >> 1);
                                } else {
                                    idx = (warp_m * 4 + wm * 2 + (r >> 1)) * 256 + ntl * 64
                                        + ((2 * tid + (r & 1)) * 4 + (g & 3)) * 2 + (g >> 2);
                                }
                                Bs[idx] = to_tf32(a);
                            }
                        }
                    }
                }
                __syncthreads();
                float* dst = outbuf + ((size_t)(iblk * 4 + h)) * 8192 + half * 4096;
#pragma unroll
                for (int it = 0; it < 4; it++) {
                    int f4 = t + it * 256;
                    *(float4*)&dst[f4 * 4] = *(const float4*)&Bs[f4 * 4];
                }
                __syncthreads();
            }
        }
    }
}

// ---------------- tf32 GEMM (final output projection) -----------------------
__global__ __launch_bounds__(256) void gemm_tf32_kernel(const float* __restrict__ Xp,
                                                        int wsel,
                                                        float* __restrict__ out,
                                                        int mode,
                                                        const float* __restrict__ bias) {
    __shared__ float As[8][512];
    __shared__ float Bs[4096];

    int t = threadIdx.x;
    int lane = t & 31;
    int warp = t >> 5;
    int warp_m = warp >> 1;
    int warp_n = warp & 1;
    size_t mtb = (size_t)blockIdx.x * 8;
    const float* wp = g_wp + (size_t)wsel * 16384;

    float acc[2][8][4];
#pragma unroll
    for (int wm = 0; wm < 2; wm++)
#pragma unroll
        for (int nt = 0; nt < 8; nt++)
#pragma unroll
            for (int r = 0; r < 4; r++) acc[wm][nt][r] = 0.0f;

    for (int k0s = 0; k0s < 4; k0s++) {
#pragma unroll
        for (int it = 0; it < 4; it++) {
            int f4 = t + it * 256;
            int mt  = f4 >> 7;
            int off = f4 & 127;
            float4 v = *(const float4*)&Xp[((mtb + mt) * 16 + k0s * 4) * 128 + off * 4];
            *(float4*)&As[mt][off * 4] = v;
        }
#pragma unroll
        for (int it = 0; it < 4; it++) {
            int f4 = t + it * 256;
            float4 v = *(const float4*)&wp[k0s * 4096 + f4 * 4];
            *(float4*)&Bs[f4 * 4] = v;
        }
        __syncthreads();

#pragma unroll
        for (int ks = 0; ks < 4; ks++) {
            uint4 afr[2];
            afr[0] = *(const uint4*)&As[warp_m * 2 + 0][ks * 128 + lane * 4];
            afr[1] = *(const uint4*)&As[warp_m * 2 + 1][ks * 128 + lane * 4];
            uint2 bfr[8];
#pragma unroll
            for (int nt = 0; nt < 8; nt++)
                bfr[nt] = *(const uint2*)&Bs[ks * 1024 + (warp_n * 8 + nt) * 64 + lane * 2];
#pragma unroll
            for (int wm = 0; wm < 2; wm++)
#pragma unroll
                for (int nt = 0; nt < 8; nt++) {
                    asm volatile(
                        "mma.sync.aligned.m16n8k8.row.col.f32.tf32.tf32.f32 "
                        "{%0,%1,%2,%3}, {%4,%5,%6,%7}, {%8,%9}, {%0,%1,%2,%3};"
                        : "+f"(acc[wm][nt][0]), "+f"(acc[wm][nt][1]),
                          "+f"(acc[wm][nt][2]), "+f"(acc[wm][nt][3])
                        : "r"(afr[wm].x), "r"(afr[wm].y), "r"(afr[wm].z), "r"(afr[wm].w),
                          "r"(bfr[nt].x), "r"(bfr[nt].y));
                }
        }
        __syncthreads();
    }

    int g   = lane >> 2;
    int tid = lane & 3;
    int m0 = blockIdx.x * 128;
#pragma unroll
    for (int wm = 0; wm < 2; wm++) {
        int row0 = m0 + warp_m * 32 + wm * 16 + g;
#pragma unroll
        for (int nt = 0; nt < 8; nt++) {
            int col = warp_n * 64 + nt * 8 + tid * 2;
            float b0 = 0.f, b1 = 0.f;
            if (mode >= 2) { b0 = bias[col]; b1 = bias[col + 1]; }
            float v[4];
#pragma unroll
            for (int r = 0; r < 4; r++) {
                float a = acc[wm][nt][r];
                float bb = (r & 1) ? b1 : b0;
                if (mode == 3) a += bb;
                v[r] = a;
            }
            *(float2*)&out[(size_t)row0 * 128 + col]       = make_float2(v[0], v[1]);
            *(float2*)&out[(size_t)(row0 + 8) * 128 + col] = make_float2(v[2], v[3]);
        }
    }
}

// ---------------- bias projection (pre-multiplied by log2e) ----------------
__global__ __launch_bounds__(256) void bias_kernel(const float* __restrict__ Wb) {
    int t = threadIdx.x;
    int lane = t & 31;
    int warp = t >> 5;
    int n = blockIdx.x * 8 + warp;
    float4 xv = *(const float4*)&g_x[(size_t)n * D + lane * 4];
    float xs[4] = {xv.x, xv.y, xv.z, xv.w};
    float p0 = 0.f, p1 = 0.f, p2 = 0.f, p3 = 0.f;
#pragma unroll
    for (int q = 0; q < 4; q++) {
        float4 wb = *(const float4*)&Wb[(lane * 4 + q) * H];
        p0 += xs[q] * wb.x;
        p1 += xs[q] * wb.y;
        p2 += xs[q] * wb.z;
        p3 += xs[q] * wb.w;
    }
#pragma unroll
    for (int off = 16; off > 0; off >>= 1) {
        p0 += __shfl_xor_sync(0xffffffffu, p0, off);
        p1 += __shfl_xor_sync(0xffffffffu, p1, off);
        p2 += __shfl_xor_sync(0xffffffffu, p2, off);
        p3 += __shfl_xor_sync(0xffffffffu, p3, off);
    }
    if (lane == 0) {
        g_bias[0 * NROW + n] = p0 * LOG2E;
        g_bias[1 * NROW + n] = p1 * LOG2E;
        g_bias[2 * NROW + n] = p2 * LOG2E;
        g_bias[3 * NROW + n] = p3 * LOG2E;
    }
}

// ---------------- tensor-core attention -------------------------------------
// grid (i=256, jt=2, h=4); 8 warps; warp handles 16 j-rows. Output written
// directly in A-fragment order (per-warp 512-float contiguous region).
__global__ __launch_bounds__(256) void attn_mma_kernel() {
    __shared__ float Pbuf[8][512];

    int t = threadIdx.x;
    int lane = t & 31;
    int warp = t >> 5;
    int g  = lane >> 2;
    int tq = lane & 3;
    int i  = blockIdx.x;
    int jt = blockIdx.y;
    int h  = blockIdx.z;

    size_t base = ((size_t)(i * 4 + h)) * 8192;
    const float* qp = g_qp + base;
    const float* kp = g_kp + base;
    const float* vp = g_vp + base;

    int mt_global = jt * 8 + warp;
    int j0 = mt_global * 16;

    uint4 qf[4];
#pragma unroll
    for (int ks = 0; ks < 4; ks++)
        qf[ks] = *(const uint4*)&qp[mt_global * 512 + ks * 128 + lane * 4];

    const float* brow0 = g_bias + (size_t)h * NROW + (size_t)(j0 + g) * 256;
    const float* brow1 = brow0 + 8 * 256;

    float lsum0 = 0.f, lsum1 = 0.f;
    float oacc[4][4];
#pragma unroll
    for (int nt = 0; nt < 4; nt++)
#pragma unroll
        for (int r = 0; r < 4; r++) oacc[nt][r] = 0.f;

    float* pb = &Pbuf[warp][0];
    int e0 = (2 * tq) & 3;
    int e1 = (2 * tq + 1) & 3;
    int rb = 2 * (tq >> 1);

    for (int c = 0; c < 8; c++) {
#pragma unroll
        for (int nt = 0; nt < 4; nt++) {
            float sacc[4] = {0.f, 0.f, 0.f, 0.f};
#pragma unroll
            for (int ks = 0; ks < 4; ks++) {
                uint2 bf = *(const uint2*)&kp[(c * 4 + nt) * 256 + ks * 64 + lane * 2];
                asm volatile(
                    "mma.sync.aligned.m16n8k8.row.col.f32.tf32.tf32.f32 "
                    "{%0,%1,%2,%3}, {%4,%5,%6,%7}, {%8,%9}, {%0,%1,%2,%3};"
                    : "+f"(sacc[0]), "+f"(sacc[1]), "+f"(sacc[2]), "+f"(sacc[3])
                    : "r"(qf[ks].x), "r"(qf[ks].y), "r"(qf[ks].z), "r"(qf[ks].w),
                      "r"(bf.x), "r"(bf.y));
            }
            int keyc = c * 32 + nt * 8 + tq * 2;
            float2 b0 = *(const float2*)&brow0[keyc];
            float2 b1 = *(const float2*)&brow1[keyc];
            float p0 = fast_ex2(sacc[0] + b0.x);
            float p1 = fast_ex2(sacc[1] + b0.y);
            float p2 = fast_ex2(sacc[2] + b1.x);
            float p3 = fast_ex2(sacc[3] + b1.y);
            lsum0 += p0 + p1;
            lsum1 += p2 + p3;
            pb[nt * 128 + (g * 4 + e0) * 4 + rb + 0] = p0;
            pb[nt * 128 + (g * 4 + e1) * 4 + rb + 0] = p1;
            pb[nt * 128 + (g * 4 + e0) * 4 + rb + 1] = p2;
            pb[nt * 128 + (g * 4 + e1) * 4 + rb + 1] = p3;
        }
        __syncwarp();
#pragma unroll
        for (int ks = 0; ks < 4; ks++) {
            uint4 pf = *(const uint4*)&pb[ks * 128 + lane * 4];
#pragma unroll
            for (int ntd = 0; ntd < 4; ntd++) {
                uint2 vf = *(const uint2*)&vp[(c * 4 + ks) * 256 + ntd * 64 + lane * 2];
                asm volatile(
                    "mma.sync.aligned.m16n8k8.row.col.f32.tf32.tf32.f32 "
                    "{%0,%1,%2,%3}, {%4,%5,%6,%7}, {%8,%9}, {%0,%1,%2,%3};"
                    : "+f"(oacc[ntd][0]), "+f"(oacc[ntd][1]),
                      "+f"(oacc[ntd][2]), "+f"(oacc[ntd][3])
                    : "r"(pf.x), "r"(pf.y), "r"(pf.z), "r"(pf.w),
                      "r"(vf.x), "r"(vf.y));
            }
        }
        __syncwarp();
    }

    lsum0 += __shfl_xor_sync(0xffffffffu, lsum0, 1);
    lsum0 += __shfl_xor_sync(0xffffffffu, lsum0, 2);
    lsum1 += __shfl_xor_sync(0xffffffffu, lsum1, 1);
    lsum1 += __shfl_xor_sync(0xffffffffu, lsum1, 2);
    float inv0 = 1.0f / lsum0;
    float inv1 = 1.0f / lsum1;

    // gated output -> A-fragment staging (inverse permute_a map), then
    // contiguous 512-float store
    size_t row0 = (size_t)(i * 256 + j0 + g) * 128 + h * 32;
    size_t row1 = row0 + 8 * 128;
#pragma unroll
    for (int ntd = 0; ntd < 4; ntd++) {
        int col = ntd * 8 + tq * 2;
        float2 g0 = *(const float2*)&g_gate[row0 + col];
        float2 g1 = *(const float2*)&g_gate[row1 + col];
        float v0 = oacc[ntd][0] * inv0 * g0.x;
        float v1 = oacc[ntd][1] * inv0 * g0.y;
        float v2 = oacc[ntd][2] * inv1 * g1.x;
        float v3 = oacc[ntd][3] * inv1 * g1.y;
        pb[ntd * 128 + (g * 4 + e0) * 4 + 0 + 2 * (tq >> 1)] = to_tf32(v0);
        pb[ntd * 128 + (g * 4 + e1) * 4 + 0 + 2 * (tq >> 1)] = to_tf32(v1);
        pb[ntd * 128 + (g * 4 + e0) * 4 + 1 + 2 * (tq >> 1)] = to_tf32(v2);
        pb[ntd * 128 + (g * 4 + e1) * 4 + 1 + 2 * (tq >> 1)] = to_tf32(v3);
    }
    __syncwarp();
    size_t tile = (size_t)(i * 16 + mt_global);
    float* dst = g_goutp + tile * 2048 + h * 512;
#pragma unroll
    for (int q = 0; q < 4; q++) {
        *(float4*)&dst[(q * 32 + lane) * 4] = *(const float4*)&pb[(q * 32 + lane) * 4];
    }
}

// ---------------- launch ----------------------------------------------------
extern "C" void kernel_launch(void* const* d_in, const int* in_sizes, int n_in,
                              void* d_out, int out_size) {
    const float* pair = (const float*)d_in[0];
    const float* ln_w = (const float*)d_in[1];
    const float* ln_b = (const float*)d_in[2];
    const float* Wq   = (const float*)d_in[3];
    const float* Wk   = (const float*)d_in[4];
    const float* Wv   = (const float*)d_in[5];
    const float* Wb   = (const float*)d_in[6];
    const float* Wg   = (const float*)d_in[7];
    const float* bg   = (const float*)d_in[8];
    const float* Wo   = (const float*)d_in[9];
    const float* bo   = (const float*)d_in[10];
    float* out = (float*)d_out;

    float *px, *pxp, *pgoutp;
    cudaGetSymbolAddress((void**)&px,     g_x);
    cudaGetSymbolAddress((void**)&pxp,    g_xp);
    cudaGetSymbolAddress((void**)&pgoutp, g_goutp);

    cudaFuncSetAttribute(proj_fused_kernel, cudaFuncAttributeMaxDynamicSharedMemorySize,
                         (16384 + 4096) * (int)sizeof(float));

    ln_kernel<<<NROW / 8, 256>>>(pair, ln_w, ln_b);
    permute_w_kernel<<<5, 256>>>(Wq, Wk, Wv, Wg, Wo);
    permute_a_kernel<<<NROW / 16, 256>>>(px, pxp);

    proj_fused_kernel<<<NROW / 128, 256, (16384 + 4096) * sizeof(float)>>>(pxp, bg);
    bias_kernel<<<NROW / 8, 256>>>(Wb);

    attn_mma_kernel<<<dim3(L, 2, H), 256>>>();

    gemm_tf32_kernel<<<NROW / 128, 256>>>(pgoutp, 4, out, 3, bo);
}